// round 6
// baseline (speedup 1.0000x reference)
#include <cuda_runtime.h>
#include <cuda_bf16.h>
#include <math.h>
#include <stdint.h>

#define BATCH 8
#define CH    256
#define NPIX  4096
#define QKVC  768
#define GROUPS 8
#define CPG    32
#define EPS    1e-5f
// fold (1/sqrt(256)) * log2(e) into q so softmax uses exp2
#define QK_FOLD 0.0901687145f

// ---------------- scratch (device globals; no runtime allocation) ----------------
__device__ __align__(16) unsigned short g_q[BATCH * NPIX * CH];   // bf16 [b][n][c], q*QK_FOLD
__device__ __align__(16) unsigned short g_k[BATCH * NPIX * CH];   // bf16 [b][n][c]
__device__ __align__(16) unsigned short g_v[BATCH * CH * NPIX];   // bf16 [b][c][n]
__device__ __align__(16) float g_attn[BATCH * NPIX * CH];         // fp32(tf32) [b][n][c]
__device__ __align__(16) float g_wb  [BATCH * QKVC * CH];         // tf32-rounded folded weights [b][o][c]
__device__ float g_bb  [BATCH * QKVC];
__device__ float g_s   [BATCH * CH];
__device__ float g_t   [BATCH * CH];

// ================= helpers =================
__device__ __forceinline__ uint32_t smem_u32(const void* p) {
    uint32_t a;
    asm("{ .reg .u64 t; cvta.to.shared.u64 t, %1; cvt.u32.u64 %0, t; }" : "=r"(a) : "l"(p));
    return a;
}
__device__ __forceinline__ float ex2f(float x) {
    float r; asm("ex2.approx.f32 %0, %1;" : "=f"(r) : "f"(x)); return r;
}
__device__ __forceinline__ float tf32r(float x) {
    float r; asm("cvt.rna.tf32.f32 %0, %1;" : "=f"(r) : "f"(x)); return r;
}
__device__ __forceinline__ void ldsm4(uint32_t& r0, uint32_t& r1, uint32_t& r2, uint32_t& r3,
                                      uint32_t addr) {
    asm volatile("ldmatrix.sync.aligned.m8n8.x4.shared.b16 {%0,%1,%2,%3}, [%4];"
                 : "=r"(r0), "=r"(r1), "=r"(r2), "=r"(r3) : "r"(addr));
}
__device__ __forceinline__ void mma_bf16(float* d, uint32_t a0, uint32_t a1, uint32_t a2,
                                         uint32_t a3, uint32_t b0, uint32_t b1) {
    asm volatile("mma.sync.aligned.m16n8k16.row.col.f32.bf16.bf16.f32 "
                 "{%0,%1,%2,%3}, {%4,%5,%6,%7}, {%8,%9}, {%0,%1,%2,%3};"
                 : "+f"(d[0]), "+f"(d[1]), "+f"(d[2]), "+f"(d[3])
                 : "r"(a0), "r"(a1), "r"(a2), "r"(a3), "r"(b0), "r"(b1));
}
__device__ __forceinline__ void mma_tf32(float* d, const uint32_t* a, const uint32_t* b) {
    asm volatile("mma.sync.aligned.m16n8k8.row.col.f32.tf32.tf32.f32 "
                 "{%0,%1,%2,%3}, {%4,%5,%6,%7}, {%8,%9}, {%0,%1,%2,%3};"
                 : "+f"(d[0]), "+f"(d[1]), "+f"(d[2]), "+f"(d[3])
                 : "r"(a[0]), "r"(a[1]), "r"(a[2]), "r"(a[3]), "r"(b[0]), "r"(b[1]));
}
#define CP_ASYNC(dst, src) \
    asm volatile("cp.async.cg.shared.global [%0], [%1], 16;" :: "r"(dst), "l"(src))
#define CP_COMMIT() asm volatile("cp.async.commit_group;" ::: "memory")
#define CP_WAIT0()  asm volatile("cp.async.wait_group 0;" ::: "memory")

// ---------------- K0: groupnorm stats ----------------
__global__ void gn_stats_kernel(const float* __restrict__ x,
                                const float* __restrict__ gamma,
                                const float* __restrict__ beta) {
    int bg = blockIdx.x;
    int b = bg >> 3, g = bg & 7;
    const float4* xv = (const float4*)(x + ((size_t)b * CH + g * CPG) * NPIX);
    float s = 0.f, s2 = 0.f;
    for (int i = threadIdx.x; i < 32768; i += 256) {
        float4 v = xv[i];
        s  += v.x + v.y + v.z + v.w;
        s2 += v.x*v.x + v.y*v.y + v.z*v.z + v.w*v.w;
    }
    __shared__ float rs[256], rs2[256];
    rs[threadIdx.x] = s; rs2[threadIdx.x] = s2;
    __syncthreads();
    for (int o = 128; o > 0; o >>= 1) {
        if (threadIdx.x < o) { rs[threadIdx.x] += rs[threadIdx.x+o]; rs2[threadIdx.x] += rs2[threadIdx.x+o]; }
        __syncthreads();
    }
    if (threadIdx.x < CPG) {
        float mean = rs[0]  * (1.0f / 131072.0f);
        float var  = rs2[0] * (1.0f / 131072.0f) - mean * mean;
        float rinv = rsqrtf(var + EPS);
        int c = g * CPG + threadIdx.x;
        float sc = rinv * gamma[c];
        g_s[b * CH + c] = sc;
        g_t[b * CH + c] = beta[c] - mean * sc;
    }
}

// ---------------- K1: fold affine into qkv weights (tf32-rounded) ----------------
__global__ void build_wb_kernel(const float* __restrict__ w_qkv,
                                const float* __restrict__ b_qkv) {
    int o = blockIdx.x, b = blockIdx.y, c = threadIdx.x;
    float w = w_qkv[o * CH + c];
    g_wb[((size_t)b * QKVC + o) * CH + c] = tf32r(w * g_s[b * CH + c]);
    __shared__ float red[256];
    red[c] = w * g_t[b * CH + c];
    __syncthreads();
    for (int off = 128; off > 0; off >>= 1) {
        if (c < off) red[c] += red[c + off];
        __syncthreads();
    }
    if (c == 0) g_bb[b * QKVC + o] = b_qkv[o] + red[0];
}

// ---------------- K2: QKV GEMM (tf32 mma) -> bf16 q/k [n][c], v [c][n] ----------------
#define QKV_SMEM ((2*32*136 + 2*128*36) * 4)

__device__ __forceinline__ void qkv_issue(float* Xs, float* Ws,
                                          const float* xb, const float* wb,
                                          int s, int n0, int o0, int tid) {
    int k0 = s * 32, buf = s & 1;
    uint32_t xdst = smem_u32(Xs + buf * 32*136);
    uint32_t wdst = smem_u32(Ws + buf * 128*36);
    #pragma unroll
    for (int it = 0; it < 4; ++it) {
        int tt = it * 256 + tid;
        int r = tt >> 5, ch = tt & 31;
        CP_ASYNC(xdst + r*544 + ch*16, xb + (size_t)(k0 + r)*NPIX + n0 + ch*4);
    }
    #pragma unroll
    for (int it = 0; it < 4; ++it) {
        int tt = it * 256 + tid;
        int r = tt >> 3, ch = tt & 7;
        CP_ASYNC(wdst + r*144 + ch*16, wb + (size_t)(o0 + r)*CH + k0 + ch*4);
    }
}

__global__ __launch_bounds__(256, 2) void qkv_tf32_kernel(const float* __restrict__ x) {
    extern __shared__ float smf[];
    float* Xs = smf;
    float* Ws = smf + 2*32*136;
    int tid = threadIdx.x, lane = tid & 31, w = tid >> 5;
    int wm = w & 1, wn = w >> 1;
    int g = lane >> 2, t = lane & 3;
    int b = blockIdx.z, o0 = blockIdx.y * 128, n0 = blockIdx.x * 128;
    const float* xb = x    + (size_t)b * CH   * NPIX;
    const float* wb = g_wb + (size_t)b * QKVC * CH;

    qkv_issue(Xs, Ws, xb, wb, 0, n0, o0, tid);
    CP_COMMIT();

    float acc[4][4][4];
    #pragma unroll
    for (int mb = 0; mb < 4; ++mb)
        #pragma unroll
        for (int nb = 0; nb < 4; ++nb)
            #pragma unroll
            for (int i = 0; i < 4; ++i) acc[mb][nb][i] = 0.f;

    for (int s = 0; s < 8; ++s) {
        CP_WAIT0();
        __syncthreads();
        if (s < 7) { qkv_issue(Xs, Ws, xb, wb, s + 1, n0, o0, tid); CP_COMMIT(); }
        const float* X = Xs + (s & 1) * 32*136;
        const float* W = Ws + (s & 1) * 128*36;
        const float* ap = X + t*136 + wm*64 + g;
        const float* bp = W + (wn*32 + g)*36 + t;
        #pragma unroll
        for (int ks = 0; ks < 4; ++ks) {
            uint32_t A[4][4], B[4][2];
            #pragma unroll
            for (int mb = 0; mb < 4; ++mb) {
                const float* a = ap + ks*1088 + mb*16;
                A[mb][0] = __float_as_uint(tf32r(a[0]));
                A[mb][1] = __float_as_uint(tf32r(a[8]));
                A[mb][2] = __float_as_uint(tf32r(a[544]));
                A[mb][3] = __float_as_uint(tf32r(a[552]));
            }
            #pragma unroll
            for (int nb = 0; nb < 4; ++nb) {
                const float* bq = bp + nb*288 + ks*8;
                B[nb][0] = __float_as_uint(bq[0]);
                B[nb][1] = __float_as_uint(bq[4]);
            }
            #pragma unroll
            for (int mb = 0; mb < 4; ++mb)
                #pragma unroll
                for (int nb = 0; nb < 4; ++nb)
                    mma_tf32(acc[mb][nb], A[mb], B[nb]);
        }
    }

    int otile = blockIdx.y;
    if (otile < 4) {
        float fold = (otile < 2) ? QK_FOLD : 1.0f;
        unsigned short* dst = ((otile < 2) ? g_q : g_k) + (size_t)b * NPIX * CH;
        int obase = (otile < 2) ? o0 : (o0 - 256);
        #pragma unroll
        for (int nb = 0; nb < 4; ++nb) {
            int oo = o0 + wn*32 + nb*8 + 2*t;
            float2 bias = *(const float2*)&g_bb[b * QKVC + oo];
            int ol = obase + wn*32 + nb*8 + 2*t;
            #pragma unroll
            for (int mb = 0; mb < 4; ++mb) {
                int nr = n0 + wm*64 + mb*16 + g;
                __nv_bfloat162 h0 = __floats2bfloat162_rn((acc[mb][nb][0] + bias.x) * fold,
                                                          (acc[mb][nb][1] + bias.y) * fold);
                __nv_bfloat162 h1 = __floats2bfloat162_rn((acc[mb][nb][2] + bias.x) * fold,
                                                          (acc[mb][nb][3] + bias.y) * fold);
                *(__nv_bfloat162*)(dst + (size_t)nr * CH + ol)       = h0;
                *(__nv_bfloat162*)(dst + (size_t)(nr + 8) * CH + ol) = h1;
            }
        }
    } else {
        unsigned short* dst = g_v + (size_t)b * CH * NPIX;
        #pragma unroll
        for (int nb = 0; nb < 4; ++nb) {
            int oo = o0 + wn*32 + nb*8 + 2*t;
            float2 bias = *(const float2*)&g_bb[b * QKVC + oo];
            int cc = (o0 - 512) + wn*32 + nb*8 + 2*t;
            #pragma unroll
            for (int mb = 0; mb < 4; ++mb) {
                int nr = n0 + wm*64 + mb*16 + g;
                __nv_bfloat16 v0 = __float2bfloat16(acc[mb][nb][0] + bias.x);
                __nv_bfloat16 v1 = __float2bfloat16(acc[mb][nb][1] + bias.y);
                __nv_bfloat16 v2 = __float2bfloat16(acc[mb][nb][2] + bias.x);
                __nv_bfloat16 v3 = __float2bfloat16(acc[mb][nb][3] + bias.y);
                dst[(size_t)cc * NPIX + nr]           = *(unsigned short*)&v0;
                dst[(size_t)(cc + 1) * NPIX + nr]     = *(unsigned short*)&v1;
                dst[(size_t)cc * NPIX + nr + 8]       = *(unsigned short*)&v2;
                dst[(size_t)(cc + 1) * NPIX + nr + 8] = *(unsigned short*)&v3;
            }
        }
    }
}

// ---------------- K3: flash attention via mma.sync bf16, 4x2 warp grid ----------------
// BQ=128, BK=64, D=256. Warp (r,h): r = w&3 (32 q-rows), h = w>>2.
// S-phase: warp (r,h) computes S[32 rows][32 kv of half h]; P exchanged via smem.
// O-phase: warp (r,h) computes O[32 rows][128 d of half h] over full kv.
// SMEM: Q [128][512B] @0, K 2x[64][512B] @65536, V 2x[256][128B] @131072,
//       P [128][128B] @196608 (16KB)
#define KS_OFF 65536
#define VS_OFF 131072
#define PS_OFF 196608
#define FL_SMEM (196608 + 16384)

__device__ __forceinline__ void issue_kv(uint32_t sb, const unsigned short* kg,
                                         const unsigned short* vg, int kb, int buf, int tid) {
    int k0 = kb * 64;
    uint32_t kbase = sb + KS_OFF + buf * 32768;
    uint32_t vbase = sb + VS_OFF + buf * 32768;
    #pragma unroll
    for (int it = 0; it < 8; ++it) {
        int t = it * 256 + tid;
        int r = t >> 5, ch = t & 31;
        CP_ASYNC(kbase + r*512 + ((ch ^ (r & 7)) << 4),
                 kg + (size_t)(k0 + r) * CH + ch * 8);
    }
    #pragma unroll
    for (int it = 0; it < 8; ++it) {
        int t = it * 256 + tid;
        int r = t >> 3, ch = t & 7;
        CP_ASYNC(vbase + r*128 + ((ch ^ (r & 7)) << 4),
                 vg + (size_t)r * NPIX + k0 + ch * 8);
    }
}

__global__ __launch_bounds__(256, 1) void flash_mma_kernel() {
    extern __shared__ char sm[];
    uint32_t sb = smem_u32(sm);
    int tid = threadIdx.x, w = tid >> 5, l = tid & 31;
    int wr = w & 3, wh = w >> 2;
    int b = blockIdx.y, q0 = blockIdx.x * 128;
    const unsigned short* qg = g_q + (size_t)b * NPIX * CH;
    const unsigned short* kg = g_k + (size_t)b * NPIX * CH;
    const unsigned short* vg = g_v + (size_t)b * CH * NPIX;

    // Q tile -> smem (swizzled)
    #pragma unroll
    for (int it = 0; it < 16; ++it) {
        int t = it * 256 + tid;
        int r = t >> 5, ch = t & 31;
        uint4 val = *(const uint4*)(qg + (size_t)(q0 + r) * CH + ch * 8);
        *(uint4*)(sm + r*512 + ((ch ^ (r & 7)) << 4)) = val;
    }
    issue_kv(sb, kg, vg, 0, 0, tid);
    CP_COMMIT();

    float oacc[2][16][4];
    #pragma unroll
    for (int mi = 0; mi < 2; ++mi)
        #pragma unroll
        for (int j = 0; j < 16; ++j)
            #pragma unroll
            for (int i = 0; i < 4; ++i) oacc[mi][j][i] = 0.f;
    float lsum[2][2] = {{0.f, 0.f}, {0.f, 0.f}};

    int lg = l >> 2, lt = l & 3;
    int a_lrow = l & 15, a_lch = l >> 4;           // A-operand ldsm lane mapping
    int b_roff = (l & 7) + ((l & 16) >> 1);        // B-operand ldsm lane mapping
    int b_choff = (l >> 3) & 1;
    uint32_t pbase = sb + PS_OFF;

    for (int kb = 0; kb < 64; ++kb) {
        CP_WAIT0();
        __syncthreads();   // KV bufs ready; previous tile's O-phase (P, V reads) done
        if (kb < 63) { issue_kv(sb, kg, vg, kb + 1, (kb + 1) & 1, tid); CP_COMMIT(); }
        uint32_t kbase = sb + KS_OFF + (kb & 1) * 32768;
        uint32_t vbase = sb + VS_OFF + (kb & 1) * 32768;

        // ---- S = Q @ K^T : 32 rows x 32 kv (half wh) ----
        float sacc[2][4][4];
        #pragma unroll
        for (int mi = 0; mi < 2; ++mi)
            #pragma unroll
            for (int j = 0; j < 4; ++j)
                #pragma unroll
                for (int i = 0; i < 4; ++i) sacc[mi][j][i] = 0.f;

        #pragma unroll
        for (int kk = 0; kk < 16; ++kk) {
            uint32_t A[2][4];
            #pragma unroll
            for (int mi = 0; mi < 2; ++mi) {
                int qrow = 32*wr + 16*mi + a_lrow;
                ldsm4(A[mi][0], A[mi][1], A[mi][2], A[mi][3],
                      sb + qrow*512 + (((2*kk + a_lch) ^ (qrow & 7)) << 4));
            }
            #pragma unroll
            for (int cb = 0; cb < 2; ++cb) {
                int krow = 32*wh + 16*cb + b_roff;
                uint32_t b0, b1, b2, b3;
                ldsm4(b0, b1, b2, b3,
                      kbase + krow*512 + (((2*kk + b_choff) ^ (krow & 7)) << 4));
                #pragma unroll
                for (int mi = 0; mi < 2; ++mi) {
                    mma_bf16(sacc[mi][2*cb],   A[mi][0], A[mi][1], A[mi][2], A[mi][3], b0, b1);
                    mma_bf16(sacc[mi][2*cb+1], A[mi][0], A[mi][1], A[mi][2], A[mi][3], b2, b3);
                }
            }
        }

        // ---- softmax: exp2, accumulate row sums, write bf16 P to smem ----
        #pragma unroll
        for (int mi = 0; mi < 2; ++mi) {
            int row0 = 32*wr + 16*mi + lg;
            #pragma unroll
            for (int ni = 0; ni < 4; ++ni) {
                float e0 = ex2f(sacc[mi][ni][0]), e1 = ex2f(sacc[mi][ni][1]);
                float e2 = ex2f(sacc[mi][ni][2]), e3 = ex2f(sacc[mi][ni][3]);
                lsum[mi][0] += e0 + e1;
                lsum[mi][1] += e2 + e3;
                __nv_bfloat162 h0 = __floats2bfloat162_rn(e0, e1);
                __nv_bfloat162 h1 = __floats2bfloat162_rn(e2, e3);
                int col = 32*wh + 8*ni + 2*lt;
                int ch  = col >> 3;
                int r1  = row0 + 8;
                *(uint32_t*)(sm + PS_OFF + row0*128 + ((ch ^ (row0 & 7)) << 4) + 4*lt) = *(uint32_t*)&h0;
                *(uint32_t*)(sm + PS_OFF + r1*128   + ((ch ^ (r1  & 7)) << 4) + 4*lt) = *(uint32_t*)&h1;
            }
        }
        __syncthreads();   // P visible to all warps

        // ---- O += P @ V : 32 rows x 128 d (half wh), full 64 kv ----
        #pragma unroll
        for (int j2 = 0; j2 < 4; ++j2) {
            uint32_t A[2][4];
            #pragma unroll
            for (int mi = 0; mi < 2; ++mi) {
                int prow = 32*wr + 16*mi + a_lrow;
                ldsm4(A[mi][0], A[mi][1], A[mi][2], A[mi][3],
                      pbase + prow*128 + (((2*j2 + a_lch) ^ (prow & 7)) << 4));
            }
            #pragma unroll
            for (int nb = 0; nb < 8; ++nb) {
                int vrow = 128*wh + 16*nb + b_roff;
                uint32_t b0, b1, b2, b3;
                ldsm4(b0, b1, b2, b3,
                      vbase + vrow*128 + (((2*j2 + b_choff) ^ (vrow & 7)) << 4));
                #pragma unroll
                for (int mi = 0; mi < 2; ++mi) {
                    mma_bf16(oacc[mi][2*nb],   A[mi][0], A[mi][1], A[mi][2], A[mi][3], b0, b1);
                    mma_bf16(oacc[mi][2*nb+1], A[mi][0], A[mi][1], A[mi][2], A[mi][3], b2, b3);
                }
            }
        }
    }
    __syncthreads();   // final O-phase done; P/Q regions free for lsum exchange

    // quad-reduce lsums (over lt), exchange across kv-halves via smem
    float* LS = (float*)sm;   // [128 rows][2 halves]
    #pragma unroll
    for (int mi = 0; mi < 2; ++mi)
        #pragma unroll
        for (int rr = 0; rr < 2; ++rr) {
            float v = lsum[mi][rr];
            v += __shfl_xor_sync(0xffffffffu, v, 1);
            v += __shfl_xor_sync(0xffffffffu, v, 2);
            lsum[mi][rr] = v;
            int row = 32*wr + 16*mi + lg + 8*rr;
            LS[row*2 + wh] = v;
        }
    __syncthreads();

    // normalize + write O rows, d-half wh
    #pragma unroll
    for (int mi = 0; mi < 2; ++mi) {
        int row0 = q0 + 32*wr + 16*mi + lg;
        int lrow = 32*wr + 16*mi + lg;
        float li0 = 1.0f / (LS[lrow*2] + LS[lrow*2+1]);
        float li1 = 1.0f / (LS[(lrow+8)*2] + LS[(lrow+8)*2+1]);
        float* o0 = g_attn + ((size_t)b * NPIX + row0) * CH + 128*wh + 2*lt;
        float* o1 = o0 + 8 * CH;
        #pragma unroll
        for (int nb = 0; nb < 16; ++nb) {
            *(float2*)(o0 + nb*8) = make_float2(tf32r(oacc[mi][nb][0]*li0), tf32r(oacc[mi][nb][1]*li0));
            *(float2*)(o1 + nb*8) = make_float2(tf32r(oacc[mi][nb][2]*li1), tf32r(oacc[mi][nb][3]*li1));
        }
    }
}

// ---------------- K4: proj GEMM (tf32 mma) + residual ----------------
#define PROJ_SMEM ((2*128*36 + 2*128*36) * 4)

__device__ __forceinline__ void proj_issue(float* As, float* Ws,
                                           const float* ab, const float* wp,
                                           int s, int n0, int o0, int tid) {
    int k0 = s * 32, buf = s & 1;
    uint32_t adst = smem_u32(As + buf * 128*36);
    uint32_t wdst = smem_u32(Ws + buf * 128*36);
    #pragma unroll
    for (int it = 0; it < 4; ++it) {
        int tt = it * 256 + tid;
        int r = tt >> 3, ch = tt & 7;
        CP_ASYNC(adst + r*144 + ch*16, ab + (size_t)(n0 + r)*CH + k0 + ch*4);
    }
    #pragma unroll
    for (int it = 0; it < 4; ++it) {
        int tt = it * 256 + tid;
        int r = tt >> 3, ch = tt & 7;
        CP_ASYNC(wdst + r*144 + ch*16, wp + (size_t)(o0 + r)*CH + k0 + ch*4);
    }
}

__global__ __launch_bounds__(256, 2) void proj_tf32_kernel(const float* __restrict__ x,
                                                           const float* __restrict__ w_proj,
                                                           const float* __restrict__ b_proj,
                                                           float* __restrict__ out) {
    extern __shared__ float smf[];
    float* As = smf;
    float* Ws = smf + 2*128*36;
    int tid = threadIdx.x, lane = tid & 31, w = tid >> 5;
    int wm = w & 1, wn = w >> 1;
    int g = lane >> 2, t = lane & 3;
    int b = blockIdx.z, o0 = blockIdx.y * 128, n0 = blockIdx.x * 128;
    const float* ab = g_attn + (size_t)b * NPIX * CH;

    proj_issue(As, Ws, ab, w_proj, 0, n0, o0, tid);
    CP_COMMIT();

    float acc[4][4][4];
    #pragma unroll
    for (int mb = 0; mb < 4; ++mb)
        #pragma unroll
        for (int nb = 0; nb < 4; ++nb)
            #pragma unroll
            for (int i = 0; i < 4; ++i) acc[mb][nb][i] = 0.f;

    for (int s = 0; s < 8; ++s) {
        CP_WAIT0();
        __syncthreads();
        if (s < 7) { proj_issue(As, Ws, ab, w_proj, s + 1, n0, o0, tid); CP_COMMIT(); }
        const float* A = As + (s & 1) * 128*36;
        const float* W = Ws + (s & 1) * 128*36;
        const float* ap = A + (wm*64 + g)*36 + t;
        const float* bp = W + (wn*32 + g)*36 + t;
        #pragma unroll
        for (int ks = 0; ks < 4; ++ks) {
            uint32_t Af[4][4], Bf[4][2];
            #pragma unroll
            for (int mb = 0; mb < 4; ++mb) {
                const float* a = ap + mb*576 + ks*8;
                Af[mb][0] = __float_as_uint(a[0]);
                Af[mb][1] = __float_as_uint(a[288]);
                Af[mb][2] = __float_as_uint(a[4]);
                Af[mb][3] = __float_as_uint(a[292]);
            }
            #pragma unroll
            for (int nb = 0; nb < 4; ++nb) {
                const float* bq = bp + nb*288 + ks*8;
                Bf[nb][0] = __float_as_uint(tf32r(bq[0]));
                Bf[nb][1] = __float_as_uint(tf32r(bq[4]));
            }
            #pragma unroll
            for (int mb = 0; mb < 4; ++mb)
                #pragma unroll
                for (int nb = 0; nb < 4; ++nb)
                    mma_tf32(acc[mb][nb], Af[mb], Bf[nb]);
        }
    }

    #pragma unroll
    for (int nb = 0; nb < 4; ++nb) {
        int oo = o0 + wn*32 + nb*8 + 2*t;
        float2 bias = *(const float2*)&b_proj[oo];
        #pragma unroll
        for (int mb = 0; mb < 4; ++mb) {
            int nr = n0 + wm*64 + mb*16 + g;
            size_t i0 = ((size_t)b * CH + oo) * NPIX + nr;
            size_t i1 = i0 + NPIX;
            out[i0]     = x[i0]     + bias.x + acc[mb][nb][0];
            out[i1]     = x[i1]     + bias.y + acc[mb][nb][1];
            out[i0 + 8] = x[i0 + 8] + bias.x + acc[mb][nb][2];
            out[i1 + 8] = x[i1 + 8] + bias.y + acc[mb][nb][3];
        }
    }
}

// ---------------- launch ----------------
extern "C" void kernel_launch(void* const* d_in, const int* in_sizes, int n_in,
                              void* d_out, int out_size) {
    const float* x      = (const float*)d_in[0];
    const float* gamma  = (const float*)d_in[1];
    const float* beta   = (const float*)d_in[2];
    const float* w_qkv  = (const float*)d_in[3];
    const float* b_qkv  = (const float*)d_in[4];
    const float* w_proj = (const float*)d_in[5];
    const float* b_proj = (const float*)d_in[6];
    float* out = (float*)d_out;

    cudaFuncSetAttribute(flash_mma_kernel, cudaFuncAttributeMaxDynamicSharedMemorySize, FL_SMEM);
    cudaFuncSetAttribute(qkv_tf32_kernel, cudaFuncAttributeMaxDynamicSharedMemorySize, QKV_SMEM);
    cudaFuncSetAttribute(proj_tf32_kernel, cudaFuncAttributeMaxDynamicSharedMemorySize, PROJ_SMEM);

    gn_stats_kernel<<<BATCH * GROUPS, 256>>>(x, gamma, beta);
    build_wb_kernel<<<dim3(QKVC, BATCH), 256>>>(w_qkv, b_qkv);
    qkv_tf32_kernel<<<dim3(NPIX/128, QKVC/128, BATCH), 256, QKV_SMEM>>>(x);
    flash_mma_kernel<<<dim3(NPIX/128, BATCH), 256, FL_SMEM>>>();
    proj_tf32_kernel<<<dim3(NPIX/128, CH/128, BATCH), 256, PROJ_SMEM>>>(x, w_proj, b_proj, out);
}

// round 7
// speedup vs baseline: 1.7735x; 1.7735x over previous
#include <cuda_runtime.h>
#include <cuda_bf16.h>
#include <math.h>
#include <stdint.h>

#define BATCH 8
#define CH    256
#define NPIX  4096
#define QKVC  768
#define GROUPS 8
#define CPG    32
#define EPS    1e-5f
// fold (1/sqrt(256)) * log2(e) into q so softmax uses exp2
#define QK_FOLD 0.0901687145f

// ---------------- scratch (device globals; no runtime allocation) ----------------
__device__ __align__(16) unsigned short g_xh[BATCH * NPIX * CH];  // bf16 x^T [b][n][c]
__device__ __align__(16) unsigned short g_q[BATCH * NPIX * CH];   // bf16 [b][n][c], q*QK_FOLD
__device__ __align__(16) unsigned short g_k[BATCH * NPIX * CH];   // bf16 [b][n][c]
__device__ __align__(16) unsigned short g_v[BATCH * CH * NPIX];   // bf16 [b][c][n]
__device__ __align__(16) unsigned short g_attnh[BATCH * NPIX * CH]; // bf16 [b][n][c]
__device__ __align__(16) unsigned short g_wbh[BATCH * QKVC * CH]; // bf16 folded qkv weights [b][o][c]
__device__ __align__(16) unsigned short g_wph[CH * CH];           // bf16 w_proj [o][c]
__device__ float g_bb  [BATCH * QKVC];
__device__ float g_s   [BATCH * CH];
__device__ float g_t   [BATCH * CH];

// ================= helpers =================
__device__ __forceinline__ uint32_t smem_u32(const void* p) {
    uint32_t a;
    asm("{ .reg .u64 t; cvta.to.shared.u64 t, %1; cvt.u32.u64 %0, t; }" : "=r"(a) : "l"(p));
    return a;
}
__device__ __forceinline__ float ex2f(float x) {
    float r; asm("ex2.approx.f32 %0, %1;" : "=f"(r) : "f"(x)); return r;
}
__device__ __forceinline__ void ldsm4(uint32_t& r0, uint32_t& r1, uint32_t& r2, uint32_t& r3,
                                      uint32_t addr) {
    asm volatile("ldmatrix.sync.aligned.m8n8.x4.shared.b16 {%0,%1,%2,%3}, [%4];"
                 : "=r"(r0), "=r"(r1), "=r"(r2), "=r"(r3) : "r"(addr));
}
__device__ __forceinline__ void mma_bf16(float* d, uint32_t a0, uint32_t a1, uint32_t a2,
                                         uint32_t a3, uint32_t b0, uint32_t b1) {
    asm volatile("mma.sync.aligned.m16n8k16.row.col.f32.bf16.bf16.f32 "
                 "{%0,%1,%2,%3}, {%4,%5,%6,%7}, {%8,%9}, {%0,%1,%2,%3};"
                 : "+f"(d[0]), "+f"(d[1]), "+f"(d[2]), "+f"(d[3])
                 : "r"(a0), "r"(a1), "r"(a2), "r"(a3), "r"(b0), "r"(b1));
}
#define CP_ASYNC(dst, src) \
    asm volatile("cp.async.cg.shared.global [%0], [%1], 16;" :: "r"(dst), "l"(src))
#define CP_COMMIT() asm volatile("cp.async.commit_group;" ::: "memory")
#define CP_WAIT0()  asm volatile("cp.async.wait_group 0;" ::: "memory")

// ---------------- K0: groupnorm stats ----------------
__global__ void gn_stats_kernel(const float* __restrict__ x,
                                const float* __restrict__ gamma,
                                const float* __restrict__ beta) {
    int bg = blockIdx.x;
    int b = bg >> 3, g = bg & 7;
    const float4* xv = (const float4*)(x + ((size_t)b * CH + g * CPG) * NPIX);
    float s = 0.f, s2 = 0.f;
    for (int i = threadIdx.x; i < 32768; i += 256) {
        float4 v = xv[i];
        s  += v.x + v.y + v.z + v.w;
        s2 += v.x*v.x + v.y*v.y + v.z*v.z + v.w*v.w;
    }
    __shared__ float rs[256], rs2[256];
    rs[threadIdx.x] = s; rs2[threadIdx.x] = s2;
    __syncthreads();
    for (int o = 128; o > 0; o >>= 1) {
        if (threadIdx.x < o) { rs[threadIdx.x] += rs[threadIdx.x+o]; rs2[threadIdx.x] += rs2[threadIdx.x+o]; }
        __syncthreads();
    }
    if (threadIdx.x < CPG) {
        float mean = rs[0]  * (1.0f / 131072.0f);
        float var  = rs2[0] * (1.0f / 131072.0f) - mean * mean;
        float rinv = rsqrtf(var + EPS);
        int c = g * CPG + threadIdx.x;
        float sc = rinv * gamma[c];
        g_s[b * CH + c] = sc;
        g_t[b * CH + c] = beta[c] - mean * sc;
    }
}

// ---------------- K0b: transpose x -> bf16 [b][n][c] ----------------
__global__ void xpose_kernel(const float* __restrict__ x) {
    __shared__ float t[32][33];
    int b = blockIdx.z, c0 = blockIdx.y * 32, n0 = blockIdx.x * 32;
    const float* xb = x + ((size_t)b * CH + c0) * NPIX + n0;
    int tx = threadIdx.x, ty = threadIdx.y;     // 32 x 8
    #pragma unroll
    for (int i = 0; i < 4; ++i)
        t[ty + 8*i][tx] = xb[(size_t)(ty + 8*i) * NPIX + tx];
    __syncthreads();
    unsigned short* o = g_xh + ((size_t)b * NPIX + n0) * CH + c0;
    #pragma unroll
    for (int i = 0; i < 4; ++i) {
        __nv_bfloat16 v = __float2bfloat16(t[tx][ty + 8*i]);
        o[(size_t)(ty + 8*i) * CH + tx] = *(unsigned short*)&v;
    }
}

// ---------------- K1: fold affine into qkv weights (bf16) ----------------
__global__ void build_wb_kernel(const float* __restrict__ w_qkv,
                                const float* __restrict__ b_qkv) {
    int o = blockIdx.x, b = blockIdx.y, c = threadIdx.x;
    float w = w_qkv[o * CH + c];
    __nv_bfloat16 wh = __float2bfloat16(w * g_s[b * CH + c]);
    g_wbh[((size_t)b * QKVC + o) * CH + c] = *(unsigned short*)&wh;
    __shared__ float red[256];
    red[c] = w * g_t[b * CH + c];
    __syncthreads();
    for (int off = 128; off > 0; off >>= 1) {
        if (c < off) red[c] += red[c + off];
        __syncthreads();
    }
    if (c == 0) g_bb[b * QKVC + o] = b_qkv[o] + red[0];
}

// ---------------- K1b: w_proj -> bf16 ----------------
__global__ void wconv_kernel(const float* __restrict__ w_proj) {
    int i = blockIdx.x * 256 + threadIdx.x;
    __nv_bfloat16 v = __float2bfloat16(w_proj[i]);
    g_wph[i] = *(unsigned short*)&v;
}

// ---------------- K2: QKV GEMM (bf16 mma) ----------------
// CTA tile: M=128 pixels x N=128 out-ch, K=256 in 4 double-buffered 64-slices.
// A = x_bf16 [n][c] rows, B = Wb [o][c] rows. Both natural ldsm (row-major K).
// smem: A 2x16KB @0, B 2x16KB @32768. Warp grid 2m x 4n (warp: m64 x n32).
#define GB_SMEM 65536

__device__ __forceinline__ void gemm_issue(uint32_t sb, const unsigned short* Abase,
                                           const unsigned short* Bbase, int s, int tid) {
    int buf = s & 1, c0 = s * 64;
    uint32_t adst = sb + buf * 16384;
    uint32_t bdst = sb + 32768 + buf * 16384;
    #pragma unroll
    for (int it = 0; it < 4; ++it) {
        int t = it * 256 + tid;
        int r = t >> 3, ch = t & 7;
        CP_ASYNC(adst + r*128 + ((ch ^ (r & 7)) << 4), Abase + (size_t)r * CH + c0 + ch * 8);
    }
    #pragma unroll
    for (int it = 0; it < 4; ++it) {
        int t = it * 256 + tid;
        int r = t >> 3, ch = t & 7;
        CP_ASYNC(bdst + r*128 + ((ch ^ (r & 7)) << 4), Bbase + (size_t)r * CH + c0 + ch * 8);
    }
}

__device__ __forceinline__ void gemm_bf16_core(uint32_t sb, const unsigned short* Abase,
                                               const unsigned short* Bbase,
                                               float acc[4][4][4], int tid) {
    int l = tid & 31, w = tid >> 5;
    int wm = w & 1, wn = w >> 1;
    int a_lrow = l & 15, a_lch = l >> 4;
    int b_roff = (l & 7) + ((l & 16) >> 1);
    int b_choff = (l >> 3) & 1;

    gemm_issue(sb, Abase, Bbase, 0, tid);
    CP_COMMIT();
    for (int s = 0; s < 4; ++s) {
        CP_WAIT0();
        __syncthreads();
        if (s < 3) { gemm_issue(sb, Abase, Bbase, s + 1, tid); CP_COMMIT(); }
        uint32_t abuf = sb + (s & 1) * 16384;
        uint32_t bbuf = sb + 32768 + (s & 1) * 16384;
        #pragma unroll
        for (int kk = 0; kk < 4; ++kk) {
            uint32_t A[4][4];
            #pragma unroll
            for (int mb = 0; mb < 4; ++mb) {
                int row = wm*64 + mb*16 + a_lrow;
                ldsm4(A[mb][0], A[mb][1], A[mb][2], A[mb][3],
                      abuf + row*128 + (((2*kk + a_lch) ^ (row & 7)) << 4));
            }
            #pragma unroll
            for (int cb = 0; cb < 2; ++cb) {
                int row = wn*32 + cb*16 + b_roff;
                uint32_t b0, b1, b2, b3;
                ldsm4(b0, b1, b2, b3,
                      bbuf + row*128 + (((2*kk + b_choff) ^ (row & 7)) << 4));
                #pragma unroll
                for (int mb = 0; mb < 4; ++mb) {
                    mma_bf16(acc[mb][2*cb],   A[mb][0], A[mb][1], A[mb][2], A[mb][3], b0, b1);
                    mma_bf16(acc[mb][2*cb+1], A[mb][0], A[mb][1], A[mb][2], A[mb][3], b2, b3);
                }
            }
        }
        __syncthreads();
    }
}

__global__ __launch_bounds__(256, 2) void qkv_bf16_kernel() {
    extern __shared__ char smc[];
    uint32_t sb = smem_u32(smc);
    int tid = threadIdx.x, lane = tid & 31, w = tid >> 5;
    int wm = w & 1, wn = w >> 1;
    int g = lane >> 2, t = lane & 3;
    int b = blockIdx.z, o0 = blockIdx.y * 128, n0 = blockIdx.x * 128;
    const unsigned short* Abase = g_xh  + ((size_t)b * NPIX + n0) * CH;
    const unsigned short* Bbase = g_wbh + ((size_t)b * QKVC + o0) * CH;

    float acc[4][4][4];
    #pragma unroll
    for (int mb = 0; mb < 4; ++mb)
        #pragma unroll
        for (int nb = 0; nb < 4; ++nb)
            #pragma unroll
            for (int i = 0; i < 4; ++i) acc[mb][nb][i] = 0.f;

    gemm_bf16_core(sb, Abase, Bbase, acc, tid);

    // epilogue: route to q / k / v by o-tile (round-5 layout, m=pixel, n=o)
    int otile = blockIdx.y;
    if (otile < 4) {
        float fold = (otile < 2) ? QK_FOLD : 1.0f;
        unsigned short* dst = ((otile < 2) ? g_q : g_k) + (size_t)b * NPIX * CH;
        int obase = (otile < 2) ? o0 : (o0 - 256);
        #pragma unroll
        for (int nb = 0; nb < 4; ++nb) {
            int oo = o0 + wn*32 + nb*8 + 2*t;
            float2 bias = *(const float2*)&g_bb[b * QKVC + oo];
            int ol = obase + wn*32 + nb*8 + 2*t;
            #pragma unroll
            for (int mb = 0; mb < 4; ++mb) {
                int nr = n0 + wm*64 + mb*16 + g;
                __nv_bfloat162 h0 = __floats2bfloat162_rn((acc[mb][nb][0] + bias.x) * fold,
                                                          (acc[mb][nb][1] + bias.y) * fold);
                __nv_bfloat162 h1 = __floats2bfloat162_rn((acc[mb][nb][2] + bias.x) * fold,
                                                          (acc[mb][nb][3] + bias.y) * fold);
                *(__nv_bfloat162*)(dst + (size_t)nr * CH + ol)       = h0;
                *(__nv_bfloat162*)(dst + (size_t)(nr + 8) * CH + ol) = h1;
            }
        }
    } else {
        unsigned short* dst = g_v + (size_t)b * CH * NPIX;
        #pragma unroll
        for (int nb = 0; nb < 4; ++nb) {
            int oo = o0 + wn*32 + nb*8 + 2*t;
            float2 bias = *(const float2*)&g_bb[b * QKVC + oo];
            int cc = (o0 - 512) + wn*32 + nb*8 + 2*t;
            #pragma unroll
            for (int mb = 0; mb < 4; ++mb) {
                int nr = n0 + wm*64 + mb*16 + g;
                __nv_bfloat16 v0 = __float2bfloat16(acc[mb][nb][0] + bias.x);
                __nv_bfloat16 v1 = __float2bfloat16(acc[mb][nb][1] + bias.y);
                __nv_bfloat16 v2 = __float2bfloat16(acc[mb][nb][2] + bias.x);
                __nv_bfloat16 v3 = __float2bfloat16(acc[mb][nb][3] + bias.y);
                dst[(size_t)cc * NPIX + nr]           = *(unsigned short*)&v0;
                dst[(size_t)(cc + 1) * NPIX + nr]     = *(unsigned short*)&v1;
                dst[(size_t)cc * NPIX + nr + 8]       = *(unsigned short*)&v2;
                dst[(size_t)(cc + 1) * NPIX + nr + 8] = *(unsigned short*)&v3;
            }
        }
    }
}

// ---------------- K3: flash attention (round-5 body; bf16 attn output) ----------------
#define KS_OFF 65536
#define VS_OFF 131072
#define FL_SMEM 196608

__device__ __forceinline__ void issue_kv(uint32_t sb, const unsigned short* kg,
                                         const unsigned short* vg, int kb, int buf, int tid) {
    int k0 = kb * 64;
    uint32_t kbase = sb + KS_OFF + buf * 32768;
    uint32_t vbase = sb + VS_OFF + buf * 32768;
    #pragma unroll
    for (int it = 0; it < 8; ++it) {
        int t = it * 256 + tid;
        int r = t >> 5, ch = t & 31;
        CP_ASYNC(kbase + r*512 + ((ch ^ (r & 7)) << 4),
                 kg + (size_t)(k0 + r) * CH + ch * 8);
    }
    #pragma unroll
    for (int it = 0; it < 8; ++it) {
        int t = it * 256 + tid;
        int r = t >> 3, ch = t & 7;
        CP_ASYNC(vbase + r*128 + ((ch ^ (r & 7)) << 4),
                 vg + (size_t)r * NPIX + k0 + ch * 8);
    }
}

__global__ __launch_bounds__(256, 1) void flash_mma_kernel() {
    extern __shared__ char sm[];
    uint32_t sb = smem_u32(sm);
    int tid = threadIdx.x, w = tid >> 5, l = tid & 31;
    int b = blockIdx.y, q0 = blockIdx.x * 128;
    const unsigned short* qg = g_q + (size_t)b * NPIX * CH;
    const unsigned short* kg = g_k + (size_t)b * NPIX * CH;
    const unsigned short* vg = g_v + (size_t)b * CH * NPIX;

    #pragma unroll
    for (int it = 0; it < 16; ++it) {
        int t = it * 256 + tid;
        int r = t >> 5, ch = t & 31;
        uint4 val = *(const uint4*)(qg + (size_t)(q0 + r) * CH + ch * 8);
        *(uint4*)(sm + r*512 + ((ch ^ (r & 7)) << 4)) = val;
    }
    issue_kv(sb, kg, vg, 0, 0, tid);
    CP_COMMIT();

    float oacc[32][4];
    #pragma unroll
    for (int j = 0; j < 32; ++j)
        #pragma unroll
        for (int i = 0; i < 4; ++i) oacc[j][i] = 0.f;
    float lsum0 = 0.f, lsum1 = 0.f;

    int qa_row = 16*w + (l & 15);
    uint32_t qa_base = sb + qa_row * 512;
    int qa_x   = qa_row & 7;
    int qa_ch  = l >> 4;
    int b_roff = (l & 7) + ((l & 16) >> 1);
    int b_choff = (l >> 3) & 1;

    for (int kb = 0; kb < 64; ++kb) {
        CP_WAIT0();
        __syncthreads();
        if (kb < 63) { issue_kv(sb, kg, vg, kb + 1, (kb + 1) & 1, tid); CP_COMMIT(); }
        uint32_t kbase = sb + KS_OFF + (kb & 1) * 32768;
        uint32_t vbase = sb + VS_OFF + (kb & 1) * 32768;

        float sacc[8][4];
        #pragma unroll
        for (int j = 0; j < 8; ++j)
            #pragma unroll
            for (int i = 0; i < 4; ++i) sacc[j][i] = 0.f;

        #pragma unroll
        for (int kk = 0; kk < 16; ++kk) {
            uint32_t a0, a1, a2, a3;
            ldsm4(a0, a1, a2, a3, qa_base + (((2*kk + qa_ch) ^ qa_x) << 4));
            #pragma unroll
            for (int jb = 0; jb < 4; ++jb) {
                int row = 16*jb + b_roff;
                uint32_t addr = kbase + row*512 + (((2*kk + b_choff) ^ (row & 7)) << 4);
                uint32_t b0, b1, b2, b3;
                ldsm4(b0, b1, b2, b3, addr);
                mma_bf16(sacc[2*jb],   a0, a1, a2, a3, b0, b1);
                mma_bf16(sacc[2*jb+1], a0, a1, a2, a3, b2, b3);
            }
        }

        uint32_t pfrag[8][2];
        #pragma unroll
        for (int j = 0; j < 8; ++j) {
            float e0 = ex2f(sacc[j][0]), e1 = ex2f(sacc[j][1]);
            float e2 = ex2f(sacc[j][2]), e3 = ex2f(sacc[j][3]);
            lsum0 += e0 + e1; lsum1 += e2 + e3;
            __nv_bfloat162 h0 = __floats2bfloat162_rn(e0, e1);
            __nv_bfloat162 h1 = __floats2bfloat162_rn(e2, e3);
            pfrag[j][0] = *(uint32_t*)&h0;
            pfrag[j][1] = *(uint32_t*)&h1;
        }

        #pragma unroll
        for (int j2 = 0; j2 < 4; ++j2) {
            uint32_t a0 = pfrag[2*j2][0],   a1 = pfrag[2*j2][1];
            uint32_t a2 = pfrag[2*j2+1][0], a3 = pfrag[2*j2+1][1];
            #pragma unroll
            for (int nb = 0; nb < 16; ++nb) {
                int row = 16*nb + b_roff;
                uint32_t addr = vbase + row*128 + (((2*j2 + b_choff) ^ (row & 7)) << 4);
                uint32_t b0, b1, b2, b3;
                ldsm4(b0, b1, b2, b3, addr);
                mma_bf16(oacc[2*nb],   a0, a1, a2, a3, b0, b1);
                mma_bf16(oacc[2*nb+1], a0, a1, a2, a3, b2, b3);
            }
        }
    }

    lsum0 += __shfl_xor_sync(0xffffffffu, lsum0, 1);
    lsum0 += __shfl_xor_sync(0xffffffffu, lsum0, 2);
    lsum1 += __shfl_xor_sync(0xffffffffu, lsum1, 1);
    lsum1 += __shfl_xor_sync(0xffffffffu, lsum1, 2);
    float li0 = 1.f / lsum0, li1 = 1.f / lsum1;

    int r0 = q0 + 16*w + (l >> 2);
    unsigned short* o0 = g_attnh + ((size_t)b * NPIX + r0) * CH + 2*(l & 3);
    unsigned short* o1 = o0 + 8 * CH;
    #pragma unroll
    for (int j = 0; j < 32; ++j) {
        __nv_bfloat162 h0 = __floats2bfloat162_rn(oacc[j][0]*li0, oacc[j][1]*li0);
        __nv_bfloat162 h1 = __floats2bfloat162_rn(oacc[j][2]*li1, oacc[j][3]*li1);
        *(__nv_bfloat162*)(o0 + j*8) = h0;
        *(__nv_bfloat162*)(o1 + j*8) = h1;
    }
}

// ---------------- K4: proj GEMM (bf16 mma) + residual ----------------
__global__ __launch_bounds__(256, 2) void proj_bf16_kernel(const float* __restrict__ x,
                                                           const float* __restrict__ b_proj,
                                                           float* __restrict__ out) {
    extern __shared__ char smc[];
    uint32_t sb = smem_u32(smc);
    int tid = threadIdx.x, lane = tid & 31, w = tid >> 5;
    int wm = w & 1, wn = w >> 1;
    int g = lane >> 2, t = lane & 3;
    int b = blockIdx.z, o0 = blockIdx.y * 128, n0 = blockIdx.x * 128;
    const unsigned short* Abase = g_attnh + ((size_t)b * NPIX + n0) * CH;
    const unsigned short* Bbase = g_wph + (size_t)o0 * CH;

    float acc[4][4][4];
    #pragma unroll
    for (int mb = 0; mb < 4; ++mb)
        #pragma unroll
        for (int nb = 0; nb < 4; ++nb)
            #pragma unroll
            for (int i = 0; i < 4; ++i) acc[mb][nb][i] = 0.f;

    gemm_bf16_core(sb, Abase, Bbase, acc, tid);

    // epilogue: out[b][o][n] = x + bias + acc (round-5 proj layout)
    #pragma unroll
    for (int nb = 0; nb < 4; ++nb) {
        int oo = o0 + wn*32 + nb*8 + 2*t;
        float2 bias = *(const float2*)&b_proj[oo];
        #pragma unroll
        for (int mb = 0; mb < 4; ++mb) {
            int nr = n0 + wm*64 + mb*16 + g;
            size_t i0 = ((size_t)b * CH + oo) * NPIX + nr;
            size_t i1 = i0 + NPIX;
            out[i0]     = x[i0]     + bias.x + acc[mb][nb][0];
            out[i1]     = x[i1]     + bias.y + acc[mb][nb][1];
            out[i0 + 8] = x[i0 + 8] + bias.x + acc[mb][nb][2];
            out[i1 + 8] = x[i1 + 8] + bias.y + acc[mb][nb][3];
        }
    }
}

// ---------------- launch ----------------
extern "C" void kernel_launch(void* const* d_in, const int* in_sizes, int n_in,
                              void* d_out, int out_size) {
    const float* x      = (const float*)d_in[0];
    const float* gamma  = (const float*)d_in[1];
    const float* beta   = (const float*)d_in[2];
    const float* w_qkv  = (const float*)d_in[3];
    const float* b_qkv  = (const float*)d_in[4];
    const float* w_proj = (const float*)d_in[5];
    const float* b_proj = (const float*)d_in[6];
    float* out = (float*)d_out;

    cudaFuncSetAttribute(flash_mma_kernel, cudaFuncAttributeMaxDynamicSharedMemorySize, FL_SMEM);
    cudaFuncSetAttribute(qkv_bf16_kernel, cudaFuncAttributeMaxDynamicSharedMemorySize, GB_SMEM);
    cudaFuncSetAttribute(proj_bf16_kernel, cudaFuncAttributeMaxDynamicSharedMemorySize, GB_SMEM);

    gn_stats_kernel<<<BATCH * GROUPS, 256>>>(x, gamma, beta);
    xpose_kernel<<<dim3(NPIX/32, CH/32, BATCH), dim3(32, 8)>>>(x);
    build_wb_kernel<<<dim3(QKVC, BATCH), 256>>>(w_qkv, b_qkv);
    wconv_kernel<<<CH*CH/256, 256>>>(w_proj);
    qkv_bf16_kernel<<<dim3(NPIX/128, QKVC/128, BATCH), 256, GB_SMEM>>>();
    flash_mma_kernel<<<dim3(NPIX/128, BATCH), 256, FL_SMEM>>>();
    proj_bf16_kernel<<<dim3(NPIX/128, CH/128, BATCH), 256, GB_SMEM>>>(x, b_proj, out);
}

// round 8
// speedup vs baseline: 1.8629x; 1.0504x over previous
#include <cuda_runtime.h>
#include <cuda_bf16.h>
#include <cuda_fp16.h>
#include <math.h>
#include <stdint.h>

#define BATCH 8
#define CH    256
#define NPIX  4096
#define QKVC  768
#define GROUPS 8
#define CPG    32
#define EPS    1e-5f
// fold (1/sqrt(256)) * log2(e) into q so softmax uses exp2
#define QK_FOLD 0.0901687145f

// ---------------- scratch (device globals; no runtime allocation) ----------------
__device__ __align__(16) unsigned short g_xh[BATCH * NPIX * CH];  // bf16 x^T [b][n][c]
__device__ __align__(16) unsigned short g_q[BATCH * NPIX * CH];   // bf16 [b][n][c], q*QK_FOLD
__device__ __align__(16) unsigned short g_k[BATCH * NPIX * CH];   // bf16 [b][n][c]
__device__ __align__(16) unsigned short g_v[BATCH * CH * NPIX];   // fp16 [b][c][n]
__device__ __align__(16) unsigned short g_attnh[BATCH * NPIX * CH]; // bf16 [b][n][c]
__device__ __align__(16) unsigned short g_wbh[BATCH * QKVC * CH]; // bf16 folded qkv weights [b][o][c]
__device__ __align__(16) unsigned short g_wph[CH * CH];           // bf16 w_proj [o][c]
__device__ float g_bb  [BATCH * QKVC];
__device__ float g_s   [BATCH * CH];
__device__ float g_t   [BATCH * CH];

// ================= helpers =================
__device__ __forceinline__ uint32_t smem_u32(const void* p) {
    uint32_t a;
    asm("{ .reg .u64 t; cvta.to.shared.u64 t, %1; cvt.u32.u64 %0, t; }" : "=r"(a) : "l"(p));
    return a;
}
__device__ __forceinline__ float ex2f(float x) {
    float r; asm("ex2.approx.f32 %0, %1;" : "=f"(r) : "f"(x)); return r;
}
__device__ __forceinline__ void ldsm4(uint32_t& r0, uint32_t& r1, uint32_t& r2, uint32_t& r3,
                                      uint32_t addr) {
    asm volatile("ldmatrix.sync.aligned.m8n8.x4.shared.b16 {%0,%1,%2,%3}, [%4];"
                 : "=r"(r0), "=r"(r1), "=r"(r2), "=r"(r3) : "r"(addr));
}
__device__ __forceinline__ void mma_bf16(float* d, uint32_t a0, uint32_t a1, uint32_t a2,
                                         uint32_t a3, uint32_t b0, uint32_t b1) {
    asm volatile("mma.sync.aligned.m16n8k16.row.col.f32.bf16.bf16.f32 "
                 "{%0,%1,%2,%3}, {%4,%5,%6,%7}, {%8,%9}, {%0,%1,%2,%3};"
                 : "+f"(d[0]), "+f"(d[1]), "+f"(d[2]), "+f"(d[3])
                 : "r"(a0), "r"(a1), "r"(a2), "r"(a3), "r"(b0), "r"(b1));
}
__device__ __forceinline__ void mma_f16acc(uint32_t* d, uint32_t a0, uint32_t a1, uint32_t a2,
                                           uint32_t a3, uint32_t b0, uint32_t b1) {
    asm volatile("mma.sync.aligned.m16n8k16.row.col.f16.f16.f16.f16 "
                 "{%0,%1}, {%2,%3,%4,%5}, {%6,%7}, {%0,%1};"
                 : "+r"(d[0]), "+r"(d[1])
                 : "r"(a0), "r"(a1), "r"(a2), "r"(a3), "r"(b0), "r"(b1));
}
#define CP_ASYNC(dst, src) \
    asm volatile("cp.async.cg.shared.global [%0], [%1], 16;" :: "r"(dst), "l"(src))
#define CP_COMMIT() asm volatile("cp.async.commit_group;" ::: "memory")
#define CP_WAIT0()  asm volatile("cp.async.wait_group 0;" ::: "memory")

// ---------------- K0: groupnorm stats ----------------
__global__ void gn_stats_kernel(const float* __restrict__ x,
                                const float* __restrict__ gamma,
                                const float* __restrict__ beta) {
    int bg = blockIdx.x;
    int b = bg >> 3, g = bg & 7;
    const float4* xv = (const float4*)(x + ((size_t)b * CH + g * CPG) * NPIX);
    float s = 0.f, s2 = 0.f;
    for (int i = threadIdx.x; i < 32768; i += 256) {
        float4 v = xv[i];
        s  += v.x + v.y + v.z + v.w;
        s2 += v.x*v.x + v.y*v.y + v.z*v.z + v.w*v.w;
    }
    __shared__ float rs[256], rs2[256];
    rs[threadIdx.x] = s; rs2[threadIdx.x] = s2;
    __syncthreads();
    for (int o = 128; o > 0; o >>= 1) {
        if (threadIdx.x < o) { rs[threadIdx.x] += rs[threadIdx.x+o]; rs2[threadIdx.x] += rs2[threadIdx.x+o]; }
        __syncthreads();
    }
    if (threadIdx.x < CPG) {
        float mean = rs[0]  * (1.0f / 131072.0f);
        float var  = rs2[0] * (1.0f / 131072.0f) - mean * mean;
        float rinv = rsqrtf(var + EPS);
        int c = g * CPG + threadIdx.x;
        float sc = rinv * gamma[c];
        g_s[b * CH + c] = sc;
        g_t[b * CH + c] = beta[c] - mean * sc;
    }
}

// ---------------- K0b: transpose x -> bf16 [b][n][c] ----------------
__global__ void xpose_kernel(const float* __restrict__ x) {
    __shared__ float t[32][33];
    int b = blockIdx.z, c0 = blockIdx.y * 32, n0 = blockIdx.x * 32;
    const float* xb = x + ((size_t)b * CH + c0) * NPIX + n0;
    int tx = threadIdx.x, ty = threadIdx.y;
    #pragma unroll
    for (int i = 0; i < 4; ++i)
        t[ty + 8*i][tx] = xb[(size_t)(ty + 8*i) * NPIX + tx];
    __syncthreads();
    unsigned short* o = g_xh + ((size_t)b * NPIX + n0) * CH + c0;
    #pragma unroll
    for (int i = 0; i < 4; ++i) {
        __nv_bfloat16 v = __float2bfloat16(t[tx][ty + 8*i]);
        o[(size_t)(ty + 8*i) * CH + tx] = *(unsigned short*)&v;
    }
}

// ---------------- K1: fold affine into qkv weights (bf16) ----------------
__global__ void build_wb_kernel(const float* __restrict__ w_qkv,
                                const float* __restrict__ b_qkv) {
    int o = blockIdx.x, b = blockIdx.y, c = threadIdx.x;
    float w = w_qkv[o * CH + c];
    __nv_bfloat16 wh = __float2bfloat16(w * g_s[b * CH + c]);
    g_wbh[((size_t)b * QKVC + o) * CH + c] = *(unsigned short*)&wh;
    __shared__ float red[256];
    red[c] = w * g_t[b * CH + c];
    __syncthreads();
    for (int off = 128; off > 0; off >>= 1) {
        if (c < off) red[c] += red[c + off];
        __syncthreads();
    }
    if (c == 0) g_bb[b * QKVC + o] = b_qkv[o] + red[0];
}

// ---------------- K1b: w_proj -> bf16 ----------------
__global__ void wconv_kernel(const float* __restrict__ w_proj) {
    int i = blockIdx.x * 256 + threadIdx.x;
    __nv_bfloat16 v = __float2bfloat16(w_proj[i]);
    g_wph[i] = *(unsigned short*)&v;
}

// ---------------- K2: QKV GEMM (bf16 mma) ----------------
#define GB_SMEM 65536

__device__ __forceinline__ void gemm_issue(uint32_t sb, const unsigned short* Abase,
                                           const unsigned short* Bbase, int s, int tid) {
    int buf = s & 1, c0 = s * 64;
    uint32_t adst = sb + buf * 16384;
    uint32_t bdst = sb + 32768 + buf * 16384;
    #pragma unroll
    for (int it = 0; it < 4; ++it) {
        int t = it * 256 + tid;
        int r = t >> 3, ch = t & 7;
        CP_ASYNC(adst + r*128 + ((ch ^ (r & 7)) << 4), Abase + (size_t)r * CH + c0 + ch * 8);
    }
    #pragma unroll
    for (int it = 0; it < 4; ++it) {
        int t = it * 256 + tid;
        int r = t >> 3, ch = t & 7;
        CP_ASYNC(bdst + r*128 + ((ch ^ (r & 7)) << 4), Bbase + (size_t)r * CH + c0 + ch * 8);
    }
}

__device__ __forceinline__ void gemm_bf16_core(uint32_t sb, const unsigned short* Abase,
                                               const unsigned short* Bbase,
                                               float acc[4][4][4], int tid) {
    int l = tid & 31, w = tid >> 5;
    int wm = w & 1, wn = w >> 1;
    int a_lrow = l & 15, a_lch = l >> 4;
    int b_roff = (l & 7) + ((l & 16) >> 1);
    int b_choff = (l >> 3) & 1;

    gemm_issue(sb, Abase, Bbase, 0, tid);
    CP_COMMIT();
    for (int s = 0; s < 4; ++s) {
        CP_WAIT0();
        __syncthreads();
        if (s < 3) { gemm_issue(sb, Abase, Bbase, s + 1, tid); CP_COMMIT(); }
        uint32_t abuf = sb + (s & 1) * 16384;
        uint32_t bbuf = sb + 32768 + (s & 1) * 16384;
        #pragma unroll
        for (int kk = 0; kk < 4; ++kk) {
            uint32_t A[4][4];
            #pragma unroll
            for (int mb = 0; mb < 4; ++mb) {
                int row = wm*64 + mb*16 + a_lrow;
                ldsm4(A[mb][0], A[mb][1], A[mb][2], A[mb][3],
                      abuf + row*128 + (((2*kk + a_lch) ^ (row & 7)) << 4));
            }
            #pragma unroll
            for (int cb = 0; cb < 2; ++cb) {
                int row = wn*32 + cb*16 + b_roff;
                uint32_t b0, b1, b2, b3;
                ldsm4(b0, b1, b2, b3,
                      bbuf + row*128 + (((2*kk + b_choff) ^ (row & 7)) << 4));
                #pragma unroll
                for (int mb = 0; mb < 4; ++mb) {
                    mma_bf16(acc[mb][2*cb],   A[mb][0], A[mb][1], A[mb][2], A[mb][3], b0, b1);
                    mma_bf16(acc[mb][2*cb+1], A[mb][0], A[mb][1], A[mb][2], A[mb][3], b2, b3);
                }
            }
        }
        __syncthreads();
    }
}

__global__ __launch_bounds__(256, 2) void qkv_bf16_kernel() {
    extern __shared__ char smc[];
    uint32_t sb = smem_u32(smc);
    int tid = threadIdx.x, lane = tid & 31, w = tid >> 5;
    int wm = w & 1, wn = w >> 1;
    int g = lane >> 2, t = lane & 3;
    int b = blockIdx.z, o0 = blockIdx.y * 128, n0 = blockIdx.x * 128;
    const unsigned short* Abase = g_xh  + ((size_t)b * NPIX + n0) * CH;
    const unsigned short* Bbase = g_wbh + ((size_t)b * QKVC + o0) * CH;

    float acc[4][4][4];
    #pragma unroll
    for (int mb = 0; mb < 4; ++mb)
        #pragma unroll
        for (int nb = 0; nb < 4; ++nb)
            #pragma unroll
            for (int i = 0; i < 4; ++i) acc[mb][nb][i] = 0.f;

    gemm_bf16_core(sb, Abase, Bbase, acc, tid);

    int otile = blockIdx.y;
    if (otile < 4) {
        float fold = (otile < 2) ? QK_FOLD : 1.0f;
        unsigned short* dst = ((otile < 2) ? g_q : g_k) + (size_t)b * NPIX * CH;
        int obase = (otile < 2) ? o0 : (o0 - 256);
        #pragma unroll
        for (int nb = 0; nb < 4; ++nb) {
            int oo = o0 + wn*32 + nb*8 + 2*t;
            float2 bias = *(const float2*)&g_bb[b * QKVC + oo];
            int ol = obase + wn*32 + nb*8 + 2*t;
            #pragma unroll
            for (int mb = 0; mb < 4; ++mb) {
                int nr = n0 + wm*64 + mb*16 + g;
                __nv_bfloat162 h0 = __floats2bfloat162_rn((acc[mb][nb][0] + bias.x) * fold,
                                                          (acc[mb][nb][1] + bias.y) * fold);
                __nv_bfloat162 h1 = __floats2bfloat162_rn((acc[mb][nb][2] + bias.x) * fold,
                                                          (acc[mb][nb][3] + bias.y) * fold);
                *(__nv_bfloat162*)(dst + (size_t)nr * CH + ol)       = h0;
                *(__nv_bfloat162*)(dst + (size_t)(nr + 8) * CH + ol) = h1;
            }
        }
    } else {
        // v : fp16 [c][n]
        unsigned short* dst = g_v + (size_t)b * CH * NPIX;
        #pragma unroll
        for (int nb = 0; nb < 4; ++nb) {
            int oo = o0 + wn*32 + nb*8 + 2*t;
            float2 bias = *(const float2*)&g_bb[b * QKVC + oo];
            int cc = (o0 - 512) + wn*32 + nb*8 + 2*t;
            #pragma unroll
            for (int mb = 0; mb < 4; ++mb) {
                int nr = n0 + wm*64 + mb*16 + g;
                __half v0 = __float2half_rn(acc[mb][nb][0] + bias.x);
                __half v1 = __float2half_rn(acc[mb][nb][1] + bias.y);
                __half v2 = __float2half_rn(acc[mb][nb][2] + bias.x);
                __half v3 = __float2half_rn(acc[mb][nb][3] + bias.y);
                dst[(size_t)cc * NPIX + nr]           = *(unsigned short*)&v0;
                dst[(size_t)(cc + 1) * NPIX + nr]     = *(unsigned short*)&v1;
                dst[(size_t)cc * NPIX + nr + 8]       = *(unsigned short*)&v2;
                dst[(size_t)(cc + 1) * NPIX + nr + 8] = *(unsigned short*)&v3;
            }
        }
    }
}

// ---------------- K3: flash attention, kv-split warps, fp16 O accum ----------------
// BQ=128, BK=64, 8 warps. Warp (r,h): r = w&3 -> 32 q-rows, h = w>>2 -> kv half.
// Each warp: S(32x32), softmax, partial O(32x256) in fp16 regs. Combine once at end.
// SMEM: Q [128][512B] @0, K 2x[64][512B] @65536, V(fp16) 2x[256][128B] @131072
#define KS_OFF 65536
#define VS_OFF 131072
#define FL_SMEM 196608
#define OH_OFF 4096
#define OH_STR 528

__device__ __forceinline__ void issue_kv(uint32_t sb, const unsigned short* kg,
                                         const unsigned short* vg, int kb, int buf, int tid) {
    int k0 = kb * 64;
    uint32_t kbase = sb + KS_OFF + buf * 32768;
    uint32_t vbase = sb + VS_OFF + buf * 32768;
    #pragma unroll
    for (int it = 0; it < 8; ++it) {
        int t = it * 256 + tid;
        int r = t >> 5, ch = t & 31;
        CP_ASYNC(kbase + r*512 + ((ch ^ (r & 7)) << 4),
                 kg + (size_t)(k0 + r) * CH + ch * 8);
    }
    #pragma unroll
    for (int it = 0; it < 8; ++it) {
        int t = it * 256 + tid;
        int r = t >> 3, ch = t & 7;
        CP_ASYNC(vbase + r*128 + ((ch ^ (r & 7)) << 4),
                 vg + (size_t)r * NPIX + k0 + ch * 8);
    }
}

__global__ __launch_bounds__(256, 1) void flash_mma_kernel() {
    extern __shared__ char sm[];
    uint32_t sb = smem_u32(sm);
    int tid = threadIdx.x, w = tid >> 5, l = tid & 31;
    int wr = w & 3, wh = w >> 2;
    int b = blockIdx.y, q0 = blockIdx.x * 128;
    const unsigned short* qg = g_q + (size_t)b * NPIX * CH;
    const unsigned short* kg = g_k + (size_t)b * NPIX * CH;
    const unsigned short* vg = g_v + (size_t)b * CH * NPIX;

    #pragma unroll
    for (int it = 0; it < 16; ++it) {
        int t = it * 256 + tid;
        int r = t >> 5, ch = t & 31;
        uint4 val = *(const uint4*)(qg + (size_t)(q0 + r) * CH + ch * 8);
        *(uint4*)(sm + r*512 + ((ch ^ (r & 7)) << 4)) = val;
    }
    issue_kv(sb, kg, vg, 0, 0, tid);
    CP_COMMIT();

    uint32_t oacc[2][32][2];   // fp16x2 accumulators: [mi][n8 col of d][row-group]
    #pragma unroll
    for (int mi = 0; mi < 2; ++mi)
        #pragma unroll
        for (int c = 0; c < 32; ++c) { oacc[mi][c][0] = 0u; oacc[mi][c][1] = 0u; }
    float lsum[2][2] = {{0.f, 0.f}, {0.f, 0.f}};

    int lg = l >> 2, lt = l & 3;
    int a_lrow = l & 15, a_lch = l >> 4;
    int b_roff = (l & 7) + ((l & 16) >> 1);
    int b_choff = (l >> 3) & 1;

    for (int kb = 0; kb < 64; ++kb) {
        CP_WAIT0();
        __syncthreads();
        if (kb < 63) { issue_kv(sb, kg, vg, kb + 1, (kb + 1) & 1, tid); CP_COMMIT(); }
        uint32_t kbase = sb + KS_OFF + (kb & 1) * 32768;
        uint32_t vbase = sb + VS_OFF + (kb & 1) * 32768;

        // ---- S = Q @ K^T : 32 rows x 32 kv (half wh) ----
        float sacc[2][4][4];
        #pragma unroll
        for (int mi = 0; mi < 2; ++mi)
            #pragma unroll
            for (int j = 0; j < 4; ++j)
                #pragma unroll
                for (int i = 0; i < 4; ++i) sacc[mi][j][i] = 0.f;

        #pragma unroll
        for (int kk = 0; kk < 16; ++kk) {
            uint32_t A[2][4];
            #pragma unroll
            for (int mi = 0; mi < 2; ++mi) {
                int qrow = 32*wr + 16*mi + a_lrow;
                ldsm4(A[mi][0], A[mi][1], A[mi][2], A[mi][3],
                      sb + qrow*512 + (((2*kk + a_lch) ^ (qrow & 7)) << 4));
            }
            #pragma unroll
            for (int cb = 0; cb < 2; ++cb) {
                int krow = 32*wh + 16*cb + b_roff;
                uint32_t b0, b1, b2, b3;
                ldsm4(b0, b1, b2, b3,
                      kbase + krow*512 + (((2*kk + b_choff) ^ (krow & 7)) << 4));
                #pragma unroll
                for (int mi = 0; mi < 2; ++mi) {
                    mma_bf16(sacc[mi][2*cb],   A[mi][0], A[mi][1], A[mi][2], A[mi][3], b0, b1);
                    mma_bf16(sacc[mi][2*cb+1], A[mi][0], A[mi][1], A[mi][2], A[mi][3], b2, b3);
                }
            }
        }

        // ---- softmax: exp2, partial row sums, fp16 P fragments ----
        uint32_t pf[2][4][2];
        #pragma unroll
        for (int mi = 0; mi < 2; ++mi) {
            #pragma unroll
            for (int ni = 0; ni < 4; ++ni) {
                float e0 = ex2f(sacc[mi][ni][0]), e1 = ex2f(sacc[mi][ni][1]);
                float e2 = ex2f(sacc[mi][ni][2]), e3 = ex2f(sacc[mi][ni][3]);
                lsum[mi][0] += e0 + e1;
                lsum[mi][1] += e2 + e3;
                __half2 h0 = __floats2half2_rn(e0, e1);
                __half2 h1 = __floats2half2_rn(e2, e3);
                pf[mi][ni][0] = *(uint32_t*)&h0;
                pf[mi][ni][1] = *(uint32_t*)&h1;
            }
        }

        // ---- O += P @ V : 32 rows x 256 d over this warp's 32 kv (fp16 accum) ----
        #pragma unroll
        for (int j2 = 0; j2 < 2; ++j2) {
            int c2 = 2*(2*wh + j2) + b_choff;
            #pragma unroll
            for (int nb = 0; nb < 16; ++nb) {
                int vrow = 16*nb + b_roff;
                uint32_t b0, b1, b2, b3;
                ldsm4(b0, b1, b2, b3,
                      vbase + vrow*128 + (((c2) ^ (vrow & 7)) << 4));
                #pragma unroll
                for (int mi = 0; mi < 2; ++mi) {
                    mma_f16acc(oacc[mi][2*nb],
                               pf[mi][2*j2][0], pf[mi][2*j2][1],
                               pf[mi][2*j2+1][0], pf[mi][2*j2+1][1], b0, b1);
                    mma_f16acc(oacc[mi][2*nb+1],
                               pf[mi][2*j2][0], pf[mi][2*j2][1],
                               pf[mi][2*j2+1][0], pf[mi][2*j2+1][1], b2, b3);
                }
            }
        }
    }
    __syncthreads();   // loop done: Q/K/V smem dead, safe to reuse

    // publish partial row sums (all warps) and h=1 partial O
    float* LS = (float*)sm;   // [128 rows][2 halves]
    #pragma unroll
    for (int mi = 0; mi < 2; ++mi)
        #pragma unroll
        for (int rr = 0; rr < 2; ++rr) {
            float v = lsum[mi][rr];
            v += __shfl_xor_sync(0xffffffffu, v, 1);
            v += __shfl_xor_sync(0xffffffffu, v, 2);
            LS[(32*wr + 16*mi + lg + 8*rr)*2 + wh] = v;
        }
    if (wh == 1) {
        #pragma unroll
        for (int mi = 0; mi < 2; ++mi) {
            int r0 = 32*wr + 16*mi + lg;
            #pragma unroll
            for (int c = 0; c < 32; ++c) {
                *(uint32_t*)(sm + OH_OFF + r0*OH_STR + (c*8 + 2*lt)*2)       = oacc[mi][c][0];
                *(uint32_t*)(sm + OH_OFF + (r0+8)*OH_STR + (c*8 + 2*lt)*2)   = oacc[mi][c][1];
            }
        }
    }
    __syncthreads();

    if (wh == 0) {
        #pragma unroll
        for (int mi = 0; mi < 2; ++mi) {
            int lrow = 32*wr + 16*mi + lg;
            float li0 = 1.0f / (LS[lrow*2] + LS[lrow*2+1]);
            float li1 = 1.0f / (LS[(lrow+8)*2] + LS[(lrow+8)*2+1]);
            unsigned short* o0 = g_attnh + ((size_t)b * NPIX + q0 + lrow) * CH + 2*lt;
            unsigned short* o1 = o0 + 8 * CH;
            #pragma unroll
            for (int c = 0; c < 32; ++c) {
                uint32_t p0 = *(uint32_t*)(sm + OH_OFF + lrow*OH_STR + (c*8 + 2*lt)*2);
                uint32_t p1 = *(uint32_t*)(sm + OH_OFF + (lrow+8)*OH_STR + (c*8 + 2*lt)*2);
                float2 f0 = __half22float2(*(__half2*)&oacc[mi][c][0]);
                float2 g0 = __half22float2(*(__half2*)&p0);
                float2 f1 = __half22float2(*(__half2*)&oacc[mi][c][1]);
                float2 g1 = __half22float2(*(__half2*)&p1);
                __nv_bfloat162 h0 = __floats2bfloat162_rn((f0.x + g0.x) * li0, (f0.y + g0.y) * li0);
                __nv_bfloat162 h1 = __floats2bfloat162_rn((f1.x + g1.x) * li1, (f1.y + g1.y) * li1);
                *(uint32_t*)(o0 + c*8) = *(uint32_t*)&h0;
                *(uint32_t*)(o1 + c*8) = *(uint32_t*)&h1;
            }
        }
    }
}

// ---------------- K4: proj GEMM (bf16 mma) + residual ----------------
__global__ __launch_bounds__(256, 2) void proj_bf16_kernel(const float* __restrict__ x,
                                                           const float* __restrict__ b_proj,
                                                           float* __restrict__ out) {
    extern __shared__ char smc[];
    uint32_t sb = smem_u32(smc);
    int tid = threadIdx.x, lane = tid & 31, w = tid >> 5;
    int wm = w & 1, wn = w >> 1;
    int g = lane >> 2, t = lane & 3;
    int b = blockIdx.z, o0 = blockIdx.y * 128, n0 = blockIdx.x * 128;
    const unsigned short* Abase = g_attnh + ((size_t)b * NPIX + n0) * CH;
    const unsigned short* Bbase = g_wph + (size_t)o0 * CH;

    float acc[4][4][4];
    #pragma unroll
    for (int mb = 0; mb < 4; ++mb)
        #pragma unroll
        for (int nb = 0; nb < 4; ++nb)
            #pragma unroll
            for (int i = 0; i < 4; ++i) acc[mb][nb][i] = 0.f;

    gemm_bf16_core(sb, Abase, Bbase, acc, tid);

    #pragma unroll
    for (int nb = 0; nb < 4; ++nb) {
        int oo = o0 + wn*32 + nb*8 + 2*t;
        float2 bias = *(const float2*)&b_proj[oo];
        #pragma unroll
        for (int mb = 0; mb < 4; ++mb) {
            int nr = n0 + wm*64 + mb*16 + g;
            size_t i0 = ((size_t)b * CH + oo) * NPIX + nr;
            size_t i1 = i0 + NPIX;
            out[i0]     = x[i0]     + bias.x + acc[mb][nb][0];
            out[i1]     = x[i1]     + bias.y + acc[mb][nb][1];
            out[i0 + 8] = x[i0 + 8] + bias.x + acc[mb][nb][2];
            out[i1 + 8] = x[i1 + 8] + bias.y + acc[mb][nb][3];
        }
    }
}

// ---------------- launch ----------------
extern "C" void kernel_launch(void* const* d_in, const int* in_sizes, int n_in,
                              void* d_out, int out_size) {
    const float* x      = (const float*)d_in[0];
    const float* gamma  = (const float*)d_in[1];
    const float* beta   = (const float*)d_in[2];
    const float* w_qkv  = (const float*)d_in[3];
    const float* b_qkv  = (const float*)d_in[4];
    const float* w_proj = (const float*)d_in[5];
    const float* b_proj = (const float*)d_in[6];
    float* out = (float*)d_out;

    cudaFuncSetAttribute(flash_mma_kernel, cudaFuncAttributeMaxDynamicSharedMemorySize, FL_SMEM);
    cudaFuncSetAttribute(qkv_bf16_kernel, cudaFuncAttributeMaxDynamicSharedMemorySize, GB_SMEM);
    cudaFuncSetAttribute(proj_bf16_kernel, cudaFuncAttributeMaxDynamicSharedMemorySize, GB_SMEM);

    gn_stats_kernel<<<BATCH * GROUPS, 256>>>(x, gamma, beta);
    xpose_kernel<<<dim3(NPIX/32, CH/32, BATCH), dim3(32, 8)>>>(x);
    build_wb_kernel<<<dim3(QKVC, BATCH), 256>>>(w_qkv, b_qkv);
    wconv_kernel<<<CH*CH/256, 256>>>(w_proj);
    qkv_bf16_kernel<<<dim3(NPIX/128, QKVC/128, BATCH), 256, GB_SMEM>>>();
    flash_mma_kernel<<<dim3(NPIX/128, BATCH), 256, FL_SMEM>>>();
    proj_bf16_kernel<<<dim3(NPIX/128, CH/128, BATCH), 256, GB_SMEM>>>(x, b_proj, out);
}